// round 5
// baseline (speedup 1.0000x reference)
#include <cuda_runtime.h>
#include <cstdint>

// Problem dims (fixed by the reference)
#define TT 512
#define BB 64
#define NI 512
#define NH 1024
#define NG 4096   // 4*NH
#define NBLK 128  // persistent scan blocks (all co-resident: 128 <= 148 SMs)

// -------- scratch (static __device__: allocation-guard safe) --------
__device__ float g_xw_enc[134217728];   // [T, B, 4H]
__device__ float g_xw_dec[134217728];
__device__ float g_h[2][BB * NH];       // double-buffered hidden state (tf32-rounded)
__device__ float g_c[BB * NH];          // cell state (block-private per (b,j))
__device__ unsigned g_bar;              // grid-barrier arrival counter

// -------- tf32 helpers --------
__device__ __forceinline__ float to_tf32(float x) {
    uint32_t u;
    asm("cvt.rna.tf32.f32 %0, %1;" : "=r"(u) : "f"(x));
    return __uint_as_float(u);
}

__device__ __forceinline__ void mma8(float* c,
                                     uint32_t a0, uint32_t a1, uint32_t a2, uint32_t a3,
                                     uint32_t b0, uint32_t b1) {
    asm volatile(
        "mma.sync.aligned.m16n8k8.row.col.f32.tf32.tf32.f32 "
        "{%0,%1,%2,%3}, {%4,%5,%6,%7}, {%8,%9}, {%0,%1,%2,%3};"
        : "+f"(c[0]), "+f"(c[1]), "+f"(c[2]), "+f"(c[3])
        : "r"(a0), "r"(a1), "r"(a2), "r"(a3), "r"(b0), "r"(b1));
}

// -------- state init (h/c/barrier must be re-zeroed every call) --------
__global__ void init_state() {
    int i = blockIdx.x * blockDim.x + threadIdx.x;
    if (i < BB * NH) {
        g_h[0][i] = 0.f;
        g_h[1][i] = 0.f;
        g_c[i]    = 0.f;
    }
    if (i == 0) g_bar = 0u;
}

// ============================================================================
// Big input projection: out[M=32768, 4096] = X[M, 512] @ W^T + bias
// Block tile 128x128x32, 8 warps (2M x 4N), warp tile 64x32.  (verified R2)
// ============================================================================
__global__ void __launch_bounds__(256, 2) gemm_xw(
    const float* __restrict__ X,
    const float* __restrict__ W,
    const float* __restrict__ bias,
    int which)
{
    float* out = which ? g_xw_dec : g_xw_enc;

    __shared__ __align__(16) float As[128][36];
    __shared__ __align__(16) float Bs[128][36];

    const int tid  = threadIdx.x;
    const int warp = tid >> 5, lane = tid & 31;
    const int g    = lane >> 2, qd = lane & 3;
    const int m0   = blockIdx.y * 128, n0 = blockIdx.x * 128;
    const int wm   = (warp >> 2) * 64, wn = (warp & 3) * 32;

    float acc[4][4][4];
#pragma unroll
    for (int a = 0; a < 4; a++)
#pragma unroll
        for (int b = 0; b < 4; b++)
#pragma unroll
            for (int r = 0; r < 4; r++) acc[a][b][r] = 0.f;

    for (int k0 = 0; k0 < NI; k0 += 32) {
#pragma unroll
        for (int i = 0; i < 4; i++) {
            int q = tid + 256 * i;
            int row = q >> 3, c4 = q & 7;
            float4 v = *(const float4*)(X + (m0 + row) * NI + k0 + c4 * 4);
            v.x = to_tf32(v.x); v.y = to_tf32(v.y);
            v.z = to_tf32(v.z); v.w = to_tf32(v.w);
            *(float4*)&As[row][c4 * 4] = v;
            float4 w4 = *(const float4*)(W + (n0 + row) * NI + k0 + c4 * 4);
            w4.x = to_tf32(w4.x); w4.y = to_tf32(w4.y);
            w4.z = to_tf32(w4.z); w4.w = to_tf32(w4.w);
            *(float4*)&Bs[row][c4 * 4] = w4;
        }
        __syncthreads();

#pragma unroll
        for (int ks = 0; ks < 4; ks++) {
            int kk = ks * 8 + qd;
            uint32_t af[4][4], bf[4][2];
#pragma unroll
            for (int mt = 0; mt < 4; mt++) {
                int r = wm + mt * 16 + g;
                af[mt][0] = __float_as_uint(As[r][kk]);
                af[mt][1] = __float_as_uint(As[r + 8][kk]);
                af[mt][2] = __float_as_uint(As[r][kk + 4]);
                af[mt][3] = __float_as_uint(As[r + 8][kk + 4]);
            }
#pragma unroll
            for (int nt = 0; nt < 4; nt++) {
                int r = wn + nt * 8 + g;
                bf[nt][0] = __float_as_uint(Bs[r][kk]);
                bf[nt][1] = __float_as_uint(Bs[r][kk + 4]);
            }
#pragma unroll
            for (int mt = 0; mt < 4; mt++)
#pragma unroll
                for (int nt = 0; nt < 4; nt++)
                    mma8(acc[mt][nt], af[mt][0], af[mt][1], af[mt][2], af[mt][3],
                         bf[nt][0], bf[nt][1]);
        }
        __syncthreads();
    }

#pragma unroll
    for (int mt = 0; mt < 4; mt++) {
#pragma unroll
        for (int nt = 0; nt < 4; nt++) {
            int row = m0 + wm + mt * 16 + g;
            int col = n0 + wn + nt * 8 + qd * 2;
            float b0 = bias[col], b1 = bias[col + 1];
            out[row * NG + col]           = acc[mt][nt][0] + b0;
            out[row * NG + col + 1]       = acc[mt][nt][1] + b1;
            out[(row + 8) * NG + col]     = acc[mt][nt][2] + b0;
            out[(row + 8) * NG + col + 1] = acc[mt][nt][3] + b1;
        }
    }
}

// ============================================================================
// Persistent recurrent scan: ONE kernel does all 512 enc + 512 dec steps.
// 128 blocks x 256 threads, all co-resident -> software grid barrier.
// Block owns j-slice of 8 hidden units x 4 gates (32 W rows), all 64 batches.
// W strip lives in SMEM (tf32) for the whole phase. H staged per-step,
// double-buffered, L1-bypassed (__ldcg: h buffers mutate across steps and
// L1 is not coherent across blocks).
//
// Smem (dynamic, floats):
//   Ws [32][1028]    131584 B  (pad 1028: conflict-free B-frag reads, 16B-aligned)
//   Hs [2][64][68]    34816 B  (double-buffered 64x64 K-chunks)
//   Gs [64][36]        9216 B  (gate pre-activations)
// total 175616 B -> 1 block/SM.
// ============================================================================
#define WS_STRIDE 1028
#define HS_STRIDE 68
#define GS_STRIDE 36
#define SMEM_WS   0
#define SMEM_HS   (32 * WS_STRIDE)
#define SMEM_GS   (SMEM_HS + 2 * 64 * HS_STRIDE)
#define SCAN_SMEM_BYTES ((SMEM_GS + 64 * GS_STRIDE) * 4)

__global__ void __launch_bounds__(256, 1) lstm_scan(
    const float* __restrict__ Whh_e, const float* __restrict__ bhh_e,
    const float* __restrict__ Whh_d, const float* __restrict__ bhh_d,
    const float* __restrict__ mask,
    float* __restrict__ dec_out)
{
    extern __shared__ float sm[];
    float* Ws = sm + SMEM_WS;
    float* Hs = sm + SMEM_HS;
    float* Gs = sm + SMEM_GS;

    const int tid  = threadIdx.x;
    const int warp = tid >> 5, lane = tid & 31;
    const int g    = lane >> 2, qd = lane & 3;
    const int j0   = blockIdx.x * 8;
    const int wm   = (warp & 3) * 16;   // 4 m-tiles of 16  (64 batches)
    const int wn   = (warp >> 2) * 16;  // 2 n-tiles of 16  (32 gate rows)

    unsigned bar_target = 0;

    for (int phase = 0; phase < 2; ++phase) {
        const float* W_hh = phase ? Whh_d : Whh_e;
        const float* b_hh = phase ? bhh_d : bhh_e;
        const float* xw   = phase ? g_xw_dec : g_xw_enc;

        // ---- load this block's W strip into smem (tf32), once per phase ----
#pragma unroll 4
        for (int i = 0; i < 32; i++) {
            int q = tid + 256 * i;              // 8192 float4 total
            int r = q >> 8, c4 = q & 255;       // r: 0..31, col = c4*4
            int wrow = (r >> 3) * NH + j0 + (r & 7);
            float4 v = *(const float4*)(W_hh + wrow * NH + c4 * 4);
            v.x = to_tf32(v.x); v.y = to_tf32(v.y);
            v.z = to_tf32(v.z); v.w = to_tf32(v.w);
            *(float4*)(Ws + r * WS_STRIDE + c4 * 4) = v;
        }
        __syncthreads();

        // hoist per-thread bias (j is fixed per thread per i-slot)
        float bh[2][4];
#pragma unroll
        for (int i = 0; i < 2; i++) {
            int j = j0 + ((tid + 256 * i) & 7);
            bh[i][0] = b_hh[j];
            bh[i][1] = b_hh[NH + j];
            bh[i][2] = b_hh[2 * NH + j];
            bh[i][3] = b_hh[3 * NH + j];
        }

        for (int t = 0; t < TT; t++) {
            const float* h_in  = g_h[t & 1];        // TT even: parity continues
            float*       h_out = g_h[(t + 1) & 1];

            float acc[2][4];
#pragma unroll
            for (int nt = 0; nt < 2; nt++)
#pragma unroll
                for (int r = 0; r < 4; r++) acc[nt][r] = 0.f;

            // prefetch H chunk 0 (L1 bypass — cross-block coherence)
            float4 pre[4];
#pragma unroll
            for (int i = 0; i < 4; i++) {
                int q = tid + 256 * i;
                int row = q >> 4, c4 = q & 15;
                pre[i] = __ldcg((const float4*)(h_in + row * NH + c4 * 4));
            }

            for (int ch = 0; ch < 16; ++ch) {
                float* buf = Hs + (ch & 1) * (64 * HS_STRIDE);
#pragma unroll
                for (int i = 0; i < 4; i++) {
                    int q = tid + 256 * i;
                    int row = q >> 4, c4 = q & 15;
                    *(float4*)(buf + row * HS_STRIDE + c4 * 4) = pre[i];
                }
                __syncthreads();   // staging visible; also guards buf reuse (2-deep)
                if (ch < 15) {
#pragma unroll
                    for (int i = 0; i < 4; i++) {
                        int q = tid + 256 * i;
                        int row = q >> 4, c4 = q & 15;
                        pre[i] = __ldcg((const float4*)(h_in + row * NH +
                                                        (ch + 1) * 64 + c4 * 4));
                    }
                }
#pragma unroll
                for (int ks = 0; ks < 8; ks++) {
                    int kk = ks * 8 + qd;        // chunk-local (A)
                    int kw = ch * 64 + kk;       // absolute (W)
                    uint32_t a0 = __float_as_uint(buf[(wm + g)     * HS_STRIDE + kk]);
                    uint32_t a1 = __float_as_uint(buf[(wm + 8 + g) * HS_STRIDE + kk]);
                    uint32_t a2 = __float_as_uint(buf[(wm + g)     * HS_STRIDE + kk + 4]);
                    uint32_t a3 = __float_as_uint(buf[(wm + 8 + g) * HS_STRIDE + kk + 4]);
#pragma unroll
                    for (int nt = 0; nt < 2; nt++) {
                        const float* wr = Ws + (wn + nt * 8 + g) * WS_STRIDE;
                        uint32_t b0 = __float_as_uint(wr[kw]);
                        uint32_t b1 = __float_as_uint(wr[kw + 4]);
                        mma8(acc[nt], a0, a1, a2, a3, b0, b1);
                    }
                }
            }

            // park gate pre-activations
#pragma unroll
            for (int nt = 0; nt < 2; nt++) {
                int col = wn + nt * 8 + qd * 2;
                Gs[(wm + g)     * GS_STRIDE + col]     = acc[nt][0];
                Gs[(wm + g)     * GS_STRIDE + col + 1] = acc[nt][1];
                Gs[(wm + 8 + g) * GS_STRIDE + col]     = acc[nt][2];
                Gs[(wm + 8 + g) * GS_STRIDE + col + 1] = acc[nt][3];
            }
            __syncthreads();

            // ---- LSTM cell: 512 elements, 2 per thread ----
            const float* xwt = xw + (size_t)t * BB * NG;
#pragma unroll
            for (int i = 0; i < 2; i++) {
                int e  = tid + 256 * i;
                int b  = e >> 3;
                int jj = e & 7;
                int j  = j0 + jj;

                float zi = Gs[b * GS_STRIDE + jj]      + xwt[b * NG + j]          + bh[i][0];
                float zf = Gs[b * GS_STRIDE + 8 + jj]  + xwt[b * NG + NH + j]     + bh[i][1];
                float zg = Gs[b * GS_STRIDE + 16 + jj] + xwt[b * NG + 2 * NH + j] + bh[i][2];
                float zo = Gs[b * GS_STRIDE + 24 + jj] + xwt[b * NG + 3 * NH + j] + bh[i][3];

                float ig = 1.f / (1.f + expf(-zi));
                float fg = 1.f / (1.f + expf(-zf));
                float gg = tanhf(zg);
                float og = 1.f / (1.f + expf(-zo));

                float c_old = g_c[b * NH + j];          // block-private: L1-safe
                float cn = fg * c_old + ig * gg;
                float hn = og * tanhf(cn);

                if (phase == 0) {
                    float m  = mask[t * BB + b];
                    float ho = __ldcg(h_in + b * NH + j);
                    hn = hn * m + ho * (1.f - m);
                    cn = cn * m + c_old * (1.f - m);
                } else {
                    dec_out[(size_t)(t * BB + b) * NH + j] = hn;
                }
                __stcg(h_out + b * NH + j, to_tf32(hn));  // pre-round for next mma
                g_c[b * NH + j] = cn;
            }

            // ---- grid barrier (monotone counter; reset by init_state) ----
            bar_target += NBLK;
            __syncthreads();
            if (tid == 0) {
                __threadfence();
                atomicAdd(&g_bar, 1u);
                while (*(volatile unsigned*)&g_bar < bar_target) { }
                __threadfence();
            }
            __syncthreads();
        }
    }
}

// ============================================================================
// kernel_launch: 4 graph nodes total (init, 2x gemm, 1 persistent scan).
// ============================================================================
extern "C" void kernel_launch(void* const* d_in, const int* in_sizes, int n_in,
                              void* d_out, int out_size) {
    const float* input = (const float*)d_in[0];   // [T,B,NI]
    const float* mask  = (const float*)d_in[1];   // [T,B]
    const float* Wih_e = (const float*)d_in[2];   // [4H,NI]
    const float* Whh_e = (const float*)d_in[3];   // [4H,NH]
    const float* bih_e = (const float*)d_in[4];
    const float* bhh_e = (const float*)d_in[5];
    const float* Wih_d = (const float*)d_in[6];
    const float* Whh_d = (const float*)d_in[7];
    const float* bih_d = (const float*)d_in[8];
    const float* bhh_d = (const float*)d_in[9];
    float* out = (float*)d_out;                   // [T*B, NH]

    (void)in_sizes; (void)n_in; (void)out_size;

    static bool attr_set = false;
    if (!attr_set) {
        cudaFuncSetAttribute(lstm_scan,
                             cudaFuncAttributeMaxDynamicSharedMemorySize,
                             SCAN_SMEM_BYTES);
        attr_set = true;
    }

    // zero h/c/barrier state (mutated every run)
    init_state<<<256, 256>>>();

    // input projections for all timesteps (one big GEMM each)
    dim3 gg(NG / 128, (TT * BB) / 128);   // (32, 256)
    gemm_xw<<<gg, 256>>>(input, Wih_e, bih_e, 0);
    gemm_xw<<<gg, 256>>>(input, Wih_d, bih_d, 1);

    // full encoder + decoder scan in ONE persistent kernel
    lstm_scan<<<NBLK, 256, SCAN_SMEM_BYTES>>>(Whh_e, bhh_e, Whh_d, bhh_d,
                                              mask, out);
}

// round 6
// speedup vs baseline: 1.5076x; 1.5076x over previous
#include <cuda_runtime.h>
#include <cstdint>

// Problem dims (fixed by the reference)
#define TT 512
#define BB 64
#define NI 512
#define NH 1024
#define NG 4096   // 4*NH
#define NBLK 128  // persistent scan blocks (all co-resident: 128 <= 148 SMs)

// -------- scratch (static __device__: allocation-guard safe) --------
__device__ float g_xw_enc[134217728];   // [T, B, 4H]
__device__ float g_xw_dec[134217728];
// Hidden state, double-buffered, stored in *mma fragment order*:
//   float4 f(kt,mt,lane) = { H[mt*16+g][kt*8+qd], H[mt*16+8+g][kt*8+qd],
//                            H[mt*16+g][kt*8+qd+4], H[mt*16+8+g][kt*8+qd+4] }
//   at float index (kt*4+mt)*128 + lane*4 + slot, lane = g*4+qd.
__device__ __align__(16) float g_h[2][BB * NH];
__device__ float g_c[BB * NH];          // cell state (block-private per (b,j))
__device__ unsigned g_bar;              // grid-barrier arrival counter

// -------- tf32 helpers --------
__device__ __forceinline__ float to_tf32(float x) {
    uint32_t u;
    asm("cvt.rna.tf32.f32 %0, %1;" : "=r"(u) : "f"(x));
    return __uint_as_float(u);
}

__device__ __forceinline__ void mma8(float* c,
                                     uint32_t a0, uint32_t a1, uint32_t a2, uint32_t a3,
                                     uint32_t b0, uint32_t b1) {
    asm volatile(
        "mma.sync.aligned.m16n8k8.row.col.f32.tf32.tf32.f32 "
        "{%0,%1,%2,%3}, {%4,%5,%6,%7}, {%8,%9}, {%0,%1,%2,%3};"
        : "+f"(c[0]), "+f"(c[1]), "+f"(c[2]), "+f"(c[3])
        : "r"(a0), "r"(a1), "r"(a2), "r"(a3), "r"(b0), "r"(b1));
}

// -------- state init (h/c/barrier must be re-zeroed every call) --------
__global__ void init_state() {
    int i = blockIdx.x * blockDim.x + threadIdx.x;
    if (i < BB * NH) {
        g_h[0][i] = 0.f;      // zeros are layout-invariant
        g_h[1][i] = 0.f;
        g_c[i]    = 0.f;
    }
    if (i == 0) g_bar = 0u;
}

// ============================================================================
// Big input projection: out[M=32768, 4096] = X[M, 512] @ W^T + bias
// Block tile 128x128x32, 8 warps (2M x 4N), warp tile 64x32.  (verified R5)
// ============================================================================
__global__ void __launch_bounds__(256, 2) gemm_xw(
    const float* __restrict__ X,
    const float* __restrict__ W,
    const float* __restrict__ bias,
    int which)
{
    float* out = which ? g_xw_dec : g_xw_enc;

    __shared__ __align__(16) float As[128][36];
    __shared__ __align__(16) float Bs[128][36];

    const int tid  = threadIdx.x;
    const int warp = tid >> 5, lane = tid & 31;
    const int g    = lane >> 2, qd = lane & 3;
    const int m0   = blockIdx.y * 128, n0 = blockIdx.x * 128;
    const int wm   = (warp >> 2) * 64, wn = (warp & 3) * 32;

    float acc[4][4][4];
#pragma unroll
    for (int a = 0; a < 4; a++)
#pragma unroll
        for (int b = 0; b < 4; b++)
#pragma unroll
            for (int r = 0; r < 4; r++) acc[a][b][r] = 0.f;

    for (int k0 = 0; k0 < NI; k0 += 32) {
#pragma unroll
        for (int i = 0; i < 4; i++) {
            int q = tid + 256 * i;
            int row = q >> 3, c4 = q & 7;
            float4 v = *(const float4*)(X + (m0 + row) * NI + k0 + c4 * 4);
            v.x = to_tf32(v.x); v.y = to_tf32(v.y);
            v.z = to_tf32(v.z); v.w = to_tf32(v.w);
            *(float4*)&As[row][c4 * 4] = v;
            float4 w4 = *(const float4*)(W + (n0 + row) * NI + k0 + c4 * 4);
            w4.x = to_tf32(w4.x); w4.y = to_tf32(w4.y);
            w4.z = to_tf32(w4.z); w4.w = to_tf32(w4.w);
            *(float4*)&Bs[row][c4 * 4] = w4;
        }
        __syncthreads();

#pragma unroll
        for (int ks = 0; ks < 4; ks++) {
            int kk = ks * 8 + qd;
            uint32_t af[4][4], bf[4][2];
#pragma unroll
            for (int mt = 0; mt < 4; mt++) {
                int r = wm + mt * 16 + g;
                af[mt][0] = __float_as_uint(As[r][kk]);
                af[mt][1] = __float_as_uint(As[r + 8][kk]);
                af[mt][2] = __float_as_uint(As[r][kk + 4]);
                af[mt][3] = __float_as_uint(As[r + 8][kk + 4]);
            }
#pragma unroll
            for (int nt = 0; nt < 4; nt++) {
                int r = wn + nt * 8 + g;
                bf[nt][0] = __float_as_uint(Bs[r][kk]);
                bf[nt][1] = __float_as_uint(Bs[r][kk + 4]);
            }
#pragma unroll
            for (int mt = 0; mt < 4; mt++)
#pragma unroll
                for (int nt = 0; nt < 4; nt++)
                    mma8(acc[mt][nt], af[mt][0], af[mt][1], af[mt][2], af[mt][3],
                         bf[nt][0], bf[nt][1]);
        }
        __syncthreads();
    }

#pragma unroll
    for (int mt = 0; mt < 4; mt++) {
#pragma unroll
        for (int nt = 0; nt < 4; nt++) {
            int row = m0 + wm + mt * 16 + g;
            int col = n0 + wn + nt * 8 + qd * 2;
            float b0 = bias[col], b1 = bias[col + 1];
            out[row * NG + col]           = acc[mt][nt][0] + b0;
            out[row * NG + col + 1]       = acc[mt][nt][1] + b1;
            out[(row + 8) * NG + col]     = acc[mt][nt][2] + b0;
            out[(row + 8) * NG + col + 1] = acc[mt][nt][3] + b1;
        }
    }
}

// ============================================================================
// Persistent recurrent scan v2.
// 128 blocks x 512 threads (16 warps), all co-resident -> software grid barrier.
// Block owns j-slice of 8 hidden units x 4 gates (32 C-cols), all 64 batches.
//
// Key changes vs v1:
//  * h stored in GLOBAL fragment order -> A-fragments are single coalesced
//    LDG.128 (L1-bypassed); no Hs smem, no staging STS, A read exactly once.
//  * W strip pre-swizzled into B-fragment order in smem: one LDS.64 per frag.
//  * 16 warps = 4 m-warps x 4 K-slices (K=256 each); K-partials reduced via
//    a small smem buffer fused into the cell phase.
//
// Smem (dynamic, floats):
//   Ws  frag-order W: 512 frags * 32 lanes * float2 = 32768 f  (131072 B)
//   P   K-partials [4][64][33]                      =  8448 f  ( 33792 B)
// total 164864 B -> 1 block/SM.
// ============================================================================
#define WS_FLOATS 32768
#define P_STRIDE  33
#define SCAN_SMEM_BYTES ((WS_FLOATS + 4 * 64 * P_STRIDE) * 4)

__global__ void __launch_bounds__(512, 1) lstm_scan(
    const float* __restrict__ Whh_e, const float* __restrict__ bhh_e,
    const float* __restrict__ Whh_d, const float* __restrict__ bhh_d,
    const float* __restrict__ mask,
    float* __restrict__ dec_out)
{
    extern __shared__ float sm[];
    float* Ws = sm;                 // fragment-order W (float2 per lane)
    float* P  = sm + WS_FLOATS;     // K-split partials

    const int tid  = threadIdx.x;
    const int warp = tid >> 5, lane = tid & 31;
    const int kw   = warp >> 2;     // K-slice 0..3 (K = 256 each)
    const int mt   = warp & 3;      // m-tile 0..3 (16 batches each)
    const int j0   = blockIdx.x * 8;
    const int ktb  = kw * 32;       // first k-tile (of 8) in this slice
    const int prow = mt * 16 + (lane >> 2);
    const int pcol = (lane & 3) * 2;

    // cell-phase constants: one (b,j) element per thread
    const int cb  = tid >> 3;       // batch 0..63
    const int cjj = tid & 7;
    const int cj  = j0 + cjj;
    // fragment-order index of (cb, cj): kt = blockIdx.x for our j-slice
    const int fmt = cb >> 4, fr = cb & 15;
    const int fidx = (blockIdx.x * 4 + fmt) * 128 +
                     ((fr & 7) * 4 + (cjj & 3)) * 4 + (cjj >> 2) * 2 + (fr >> 3);

    unsigned bar_target = 0;

    for (int phase = 0; phase < 2; ++phase) {
        const float* W_hh = phase ? Whh_d : Whh_e;
        const float* b_hh = phase ? bhh_d : bhh_e;
        const float* xw   = phase ? g_xw_dec : g_xw_enc;

        // ---- rearrange W strip into B-fragment order (once per phase) ----
        // frag (kt 0..127, nt 0..3, lane): float2 { W[n][k], W[n][k+4] },
        // n = nt*NH-row mapping: C col = nt*8+g -> W row = nt*NH + j0 + g.
        for (int i = tid; i < 16384; i += 512) {
            int l2 = i & 31, f = i >> 5;
            int kt = f >> 2, nt = f & 3;
            int g2 = l2 >> 2, qd2 = l2 & 3;
            const float* wr = W_hh + (nt * NH + j0 + g2) * NH + kt * 8 + qd2;
            Ws[i * 2]     = to_tf32(wr[0]);
            Ws[i * 2 + 1] = to_tf32(wr[4]);
        }
        __syncthreads();

        float bh0 = b_hh[cj], bh1 = b_hh[NH + cj],
              bh2 = b_hh[2 * NH + cj], bh3 = b_hh[3 * NH + cj];

        for (int t = 0; t < TT; t++) {
            const float4* hf   = (const float4*)g_h[t & 1];
            const float*  h_in = g_h[t & 1];
            float*        h_out = g_h[(t + 1) & 1];

            float acc[4][4];
#pragma unroll
            for (int nt = 0; nt < 4; nt++)
#pragma unroll
                for (int r = 0; r < 4; r++) acc[nt][r] = 0.f;

            // ---- GEMM over this warp's K-slice: A direct from global ----
            float4 ab[4];
#pragma unroll
            for (int p = 0; p < 4; p++)
                ab[p] = __ldcg(hf + ((ktb + p) * 4 + mt) * 32 + lane);

#pragma unroll 4
            for (int it = 0; it < 32; ++it) {
                int kt = ktb + it;
                float4 a = ab[it & 3];
                if (it + 4 < 32)
                    ab[it & 3] = __ldcg(hf + ((kt + 4) * 4 + mt) * 32 + lane);
                uint32_t a0 = __float_as_uint(a.x), a1 = __float_as_uint(a.y);
                uint32_t a2 = __float_as_uint(a.z), a3 = __float_as_uint(a.w);
#pragma unroll
                for (int nt = 0; nt < 4; nt++) {
                    float2 wv = *(const float2*)(Ws + ((kt * 4 + nt) * 32 + lane) * 2);
                    mma8(acc[nt], a0, a1, a2, a3,
                         __float_as_uint(wv.x), __float_as_uint(wv.y));
                }
            }

            // ---- park K-partials ----
            {
                float* Pw = P + kw * (64 * P_STRIDE);
#pragma unroll
                for (int nt = 0; nt < 4; nt++) {
                    int col = nt * 8 + pcol;
                    Pw[prow * P_STRIDE + col]           = acc[nt][0];
                    Pw[prow * P_STRIDE + col + 1]       = acc[nt][1];
                    Pw[(prow + 8) * P_STRIDE + col]     = acc[nt][2];
                    Pw[(prow + 8) * P_STRIDE + col + 1] = acc[nt][3];
                }
            }
            __syncthreads();

            // ---- LSTM cell: 512 elements, 1 per thread; fuses K-reduce ----
            {
                const float* xwt = xw + (size_t)t * BB * NG + (size_t)cb * NG + cj;
                float zi = xwt[0]      + bh0;
                float zf = xwt[NH]     + bh1;
                float zg = xwt[2 * NH] + bh2;
                float zo = xwt[3 * NH] + bh3;
#pragma unroll
                for (int k = 0; k < 4; k++) {
                    const float* p = P + k * (64 * P_STRIDE) + cb * P_STRIDE;
                    zi += p[cjj];
                    zf += p[8 + cjj];
                    zg += p[16 + cjj];
                    zo += p[24 + cjj];
                }

                float ig = 1.f / (1.f + expf(-zi));
                float fg = 1.f / (1.f + expf(-zf));
                float gg = tanhf(zg);
                float og = 1.f / (1.f + expf(-zo));

                float c_old = g_c[cb * NH + cj];     // block-private: L1-safe
                float cn = fg * c_old + ig * gg;
                float hn = og * tanhf(cn);

                if (phase == 0) {
                    float m  = mask[t * BB + cb];
                    float ho = __ldcg(h_in + fidx);
                    hn = hn * m + ho * (1.f - m);
                    cn = cn * m + c_old * (1.f - m);
                } else {
                    dec_out[(size_t)(t * BB + cb) * NH + cj] = hn;
                }
                __stcg(h_out + fidx, to_tf32(hn));   // pre-round for next mma
                g_c[cb * NH + cj] = cn;
            }

            // ---- grid barrier (monotone counter; reset by init_state) ----
            bar_target += NBLK;
            __syncthreads();
            if (tid == 0) {
                __threadfence();
                atomicAdd(&g_bar, 1u);
                while (*(volatile unsigned*)&g_bar < bar_target) { }
                __threadfence();
            }
            __syncthreads();
        }
    }
}

// ============================================================================
// kernel_launch: 4 graph nodes (init, 2x gemm, 1 persistent scan).
// ============================================================================
extern "C" void kernel_launch(void* const* d_in, const int* in_sizes, int n_in,
                              void* d_out, int out_size) {
    const float* input = (const float*)d_in[0];   // [T,B,NI]
    const float* mask  = (const float*)d_in[1];   // [T,B]
    const float* Wih_e = (const float*)d_in[2];   // [4H,NI]
    const float* Whh_e = (const float*)d_in[3];   // [4H,NH]
    const float* bih_e = (const float*)d_in[4];
    const float* bhh_e = (const float*)d_in[5];
    const float* Wih_d = (const float*)d_in[6];
    const float* Whh_d = (const float*)d_in[7];
    const float* bih_d = (const float*)d_in[8];
    const float* bhh_d = (const float*)d_in[9];
    float* out = (float*)d_out;                   // [T*B, NH]

    (void)in_sizes; (void)n_in; (void)out_size;

    static bool attr_set = false;
    if (!attr_set) {
        cudaFuncSetAttribute(lstm_scan,
                             cudaFuncAttributeMaxDynamicSharedMemorySize,
                             SCAN_SMEM_BYTES);
        attr_set = true;
    }

    // zero h/c/barrier state (mutated every run)
    init_state<<<256, 256>>>();

    // input projections for all timesteps (one big GEMM each)
    dim3 gg(NG / 128, (TT * BB) / 128);   // (32, 256)
    gemm_xw<<<gg, 256>>>(input, Wih_e, bih_e, 0);
    gemm_xw<<<gg, 256>>>(input, Wih_d, bih_d, 1);

    // full encoder + decoder scan in ONE persistent kernel
    lstm_scan<<<NBLK, 512, SCAN_SMEM_BYTES>>>(Whh_e, bhh_e, Whh_d, bhh_d,
                                              mask, out);
}

// round 7
// speedup vs baseline: 1.5307x; 1.0154x over previous
#include <cuda_runtime.h>
#include <cstdint>

// Problem dims (fixed by the reference)
#define TT 512
#define BB 64
#define NI 512
#define NH 1024
#define NG 4096   // 4*NH
#define NBLK 128  // persistent scan blocks (all co-resident: 128 <= 148 SMs)

// -------- scratch (static __device__: allocation-guard safe) --------
__device__ float g_xw_enc[134217728];   // [T, B, 4H]
__device__ float g_xw_dec[134217728];
// Hidden state, double-buffered, stored in *mma fragment order* (see R5/R6).
__device__ __align__(16) float g_h[2][BB * NH];
__device__ float g_c[BB * NH];          // cell state (block-private per (b,j))
__device__ unsigned g_bar;              // grid-barrier arrival counter

// -------- tf32 helpers --------
__device__ __forceinline__ float to_tf32(float x) {
    uint32_t u;
    asm("cvt.rna.tf32.f32 %0, %1;" : "=r"(u) : "f"(x));
    return __uint_as_float(u);
}

__device__ __forceinline__ void mma8(float* c,
                                     uint32_t a0, uint32_t a1, uint32_t a2, uint32_t a3,
                                     uint32_t b0, uint32_t b1) {
    asm volatile(
        "mma.sync.aligned.m16n8k8.row.col.f32.tf32.tf32.f32 "
        "{%0,%1,%2,%3}, {%4,%5,%6,%7}, {%8,%9}, {%0,%1,%2,%3};"
        : "+f"(c[0]), "+f"(c[1]), "+f"(c[2]), "+f"(c[3])
        : "r"(a0), "r"(a1), "r"(a2), "r"(a3), "r"(b0), "r"(b1));
}

// -------- state init (h/c/barrier must be re-zeroed every call) --------
__global__ void init_state() {
    int i = blockIdx.x * blockDim.x + threadIdx.x;
    if (i < BB * NH) {
        g_h[0][i] = 0.f;      // zeros are layout-invariant
        g_h[1][i] = 0.f;
        g_c[i]    = 0.f;
    }
    if (i == 0) g_bar = 0u;
}

// ============================================================================
// Big input projection: out[M=32768, 4096] = X[M, 512] @ W^T + bias
// Block tile 128x128x32, 8 warps (2M x 4N), warp tile 64x32.  (verified)
// ============================================================================
__global__ void __launch_bounds__(256, 2) gemm_xw(
    const float* __restrict__ X,
    const float* __restrict__ W,
    const float* __restrict__ bias,
    int which)
{
    float* out = which ? g_xw_dec : g_xw_enc;

    __shared__ __align__(16) float As[128][36];
    __shared__ __align__(16) float Bs[128][36];

    const int tid  = threadIdx.x;
    const int warp = tid >> 5, lane = tid & 31;
    const int g    = lane >> 2, qd = lane & 3;
    const int m0   = blockIdx.y * 128, n0 = blockIdx.x * 128;
    const int wm   = (warp >> 2) * 64, wn = (warp & 3) * 32;

    float acc[4][4][4];
#pragma unroll
    for (int a = 0; a < 4; a++)
#pragma unroll
        for (int b = 0; b < 4; b++)
#pragma unroll
            for (int r = 0; r < 4; r++) acc[a][b][r] = 0.f;

    for (int k0 = 0; k0 < NI; k0 += 32) {
#pragma unroll
        for (int i = 0; i < 4; i++) {
            int q = tid + 256 * i;
            int row = q >> 3, c4 = q & 7;
            float4 v = *(const float4*)(X + (m0 + row) * NI + k0 + c4 * 4);
            v.x = to_tf32(v.x); v.y = to_tf32(v.y);
            v.z = to_tf32(v.z); v.w = to_tf32(v.w);
            *(float4*)&As[row][c4 * 4] = v;
            float4 w4 = *(const float4*)(W + (n0 + row) * NI + k0 + c4 * 4);
            w4.x = to_tf32(w4.x); w4.y = to_tf32(w4.y);
            w4.z = to_tf32(w4.z); w4.w = to_tf32(w4.w);
            *(float4*)&Bs[row][c4 * 4] = w4;
        }
        __syncthreads();

#pragma unroll
        for (int ks = 0; ks < 4; ks++) {
            int kk = ks * 8 + qd;
            uint32_t af[4][4], bf[4][2];
#pragma unroll
            for (int mt = 0; mt < 4; mt++) {
                int r = wm + mt * 16 + g;
                af[mt][0] = __float_as_uint(As[r][kk]);
                af[mt][1] = __float_as_uint(As[r + 8][kk]);
                af[mt][2] = __float_as_uint(As[r][kk + 4]);
                af[mt][3] = __float_as_uint(As[r + 8][kk + 4]);
            }
#pragma unroll
            for (int nt = 0; nt < 4; nt++) {
                int r = wn + nt * 8 + g;
                bf[nt][0] = __float_as_uint(Bs[r][kk]);
                bf[nt][1] = __float_as_uint(Bs[r][kk + 4]);
            }
#pragma unroll
            for (int mt = 0; mt < 4; mt++)
#pragma unroll
                for (int nt = 0; nt < 4; nt++)
                    mma8(acc[mt][nt], af[mt][0], af[mt][1], af[mt][2], af[mt][3],
                         bf[nt][0], bf[nt][1]);
        }
        __syncthreads();
    }

#pragma unroll
    for (int mt = 0; mt < 4; mt++) {
#pragma unroll
        for (int nt = 0; nt < 4; nt++) {
            int row = m0 + wm + mt * 16 + g;
            int col = n0 + wn + nt * 8 + qd * 2;
            float b0 = bias[col], b1 = bias[col + 1];
            out[row * NG + col]           = acc[mt][nt][0] + b0;
            out[row * NG + col + 1]       = acc[mt][nt][1] + b1;
            out[(row + 8) * NG + col]     = acc[mt][nt][2] + b0;
            out[(row + 8) * NG + col + 1] = acc[mt][nt][3] + b1;
        }
    }
}

// ============================================================================
// Persistent recurrent scan v3.
// 128 blocks x 512 threads (16 warps = 4 m-warps x 4 K-slices).
// Changes vs v2:
//  * Ws packed so each mma iteration reads 2x LDS.128 (nt-pairs interleaved),
//    and B fragments are register-prefetched one iteration ahead -> LDS
//    latency is off the mma dependency chain.
//  * All cell-phase operands (xw x4, c_old, mask, ho) are loaded at STEP
//    START, consumed ~5k cycles later -> DRAM/L2 latency hidden by the GEMM.
//  * Grid barrier uses red.release + ld.acquire (no MEMBAR.ALL.GPU).
// Smem: Ws 32768 f (131072 B) + P 4*64*33 f (33792 B) = 164864 B -> 1 blk/SM.
// ============================================================================
#define WS_FLOATS 32768
#define P_STRIDE  33
#define SCAN_SMEM_BYTES ((WS_FLOATS + 4 * 64 * P_STRIDE) * 4)

__global__ void __launch_bounds__(512, 1) lstm_scan(
    const float* __restrict__ Whh_e, const float* __restrict__ bhh_e,
    const float* __restrict__ Whh_d, const float* __restrict__ bhh_d,
    const float* __restrict__ mask,
    float* __restrict__ dec_out)
{
    extern __shared__ float sm[];
    float* Ws = sm;                 // fragment-order W, nt-pairs packed in float4
    float* P  = sm + WS_FLOATS;     // K-split partials

    const int tid  = threadIdx.x;
    const int warp = tid >> 5, lane = tid & 31;
    const int kw   = warp >> 2;     // K-slice 0..3 (K = 256 each)
    const int mt   = warp & 3;      // m-tile 0..3 (16 batches each)
    const int j0   = blockIdx.x * 8;
    const int ktb  = kw * 32;       // first k-tile (of 8) in this slice
    const int prow = mt * 16 + (lane >> 2);
    const int pcol = (lane & 3) * 2;

    // cell-phase constants: one (b,j) element per thread
    const int cb  = tid >> 3;       // batch 0..63
    const int cjj = tid & 7;
    const int cj  = j0 + cjj;
    const int fmt = cb >> 4, fr = cb & 15;
    const int fidx = (blockIdx.x * 4 + fmt) * 128 +
                     ((fr & 7) * 4 + (cjj & 3)) * 4 + (cjj >> 2) * 2 + (fr >> 3);

    unsigned bar_target = 0;

    for (int phase = 0; phase < 2; ++phase) {
        const float* W_hh = phase ? Whh_d : Whh_e;
        const float* b_hh = phase ? bhh_d : bhh_e;
        const float* xw   = phase ? g_xw_dec : g_xw_enc;

        // ---- rearrange W strip into packed B-fragment order (once/phase) ----
        // float4 unit u = (kt*2 + ntp)*32 + lane holds, for nt0=2*ntp, nt1=nt0+1:
        //   { W[nt0][k], W[nt0][k+4], W[nt1][k], W[nt1][k+4] }  (tf32-rounded)
        // where W row for C-col nt*8+g is (nt*NH + j0 + g), k = kt*8 + qd.
        for (int u = tid; u < 8192; u += 512) {
            int l2 = u & 31, f = u >> 5;
            int kt = f >> 1, ntp = f & 1;
            int g2 = l2 >> 2, qd2 = l2 & 3;
            const float* w0 = W_hh + ((2 * ntp)     * NH + j0 + g2) * NH + kt * 8 + qd2;
            const float* w1 = W_hh + ((2 * ntp + 1) * NH + j0 + g2) * NH + kt * 8 + qd2;
            float4 v;
            v.x = to_tf32(w0[0]); v.y = to_tf32(w0[4]);
            v.z = to_tf32(w1[0]); v.w = to_tf32(w1[4]);
            *(float4*)(Ws + u * 4) = v;
        }
        __syncthreads();

        const float bh0 = b_hh[cj], bh1 = b_hh[NH + cj],
                    bh2 = b_hh[2 * NH + cj], bh3 = b_hh[3 * NH + cj];

        for (int t = 0; t < TT; t++) {
            const float4* hf    = (const float4*)g_h[t & 1];
            const float*  h_in  = g_h[t & 1];
            float*        h_out = g_h[(t + 1) & 1];
            const float4* Ws4   = (const float4*)Ws;

            // ---- EARLY loads for the cell phase (consumed after the GEMM;
            //      DRAM/L2 latency hidden behind ~5k cycles of mma work) ----
            const float* xwt = xw + (size_t)t * BB * NG + (size_t)cb * NG + cj;
            float xv0 = xwt[0], xv1 = xwt[NH], xv2 = xwt[2 * NH], xv3 = xwt[3 * NH];
            float c_old = g_c[cb * NH + cj];
            float mval = 1.f, ho = 0.f;
            if (phase == 0) {
                mval = mask[t * BB + cb];
                ho   = __ldcg(h_in + fidx);
            }

            float acc[4][4];
#pragma unroll
            for (int nt = 0; nt < 4; nt++)
#pragma unroll
                for (int r = 0; r < 4; r++) acc[nt][r] = 0.f;

            // ---- GEMM over this warp's K-slice ----
            // A: depth-4 LDG.128 prefetch from L2 (fragment-order h).
            // B: 1-iteration register prefetch of 2x LDS.128.
            float4 ab[4];
#pragma unroll
            for (int p = 0; p < 4; p++)
                ab[p] = __ldcg(hf + ((ktb + p) * 4 + mt) * 32 + lane);
            float4 b01 = Ws4[(ktb * 2)     * 32 + lane];
            float4 b23 = Ws4[(ktb * 2 + 1) * 32 + lane];

#pragma unroll 4
            for (int it = 0; it < 32; ++it) {
                int kt = ktb + it;
                float4 a   = ab[it & 3];
                float4 w01 = b01, w23 = b23;
                if (it + 4 < 32)
                    ab[it & 3] = __ldcg(hf + ((kt + 4) * 4 + mt) * 32 + lane);
                if (it + 1 < 32) {
                    b01 = Ws4[((kt + 1) * 2)     * 32 + lane];
                    b23 = Ws4[((kt + 1) * 2 + 1) * 32 + lane];
                }
                uint32_t a0 = __float_as_uint(a.x), a1 = __float_as_uint(a.y);
                uint32_t a2 = __float_as_uint(a.z), a3 = __float_as_uint(a.w);
                mma8(acc[0], a0, a1, a2, a3,
                     __float_as_uint(w01.x), __float_as_uint(w01.y));
                mma8(acc[1], a0, a1, a2, a3,
                     __float_as_uint(w01.z), __float_as_uint(w01.w));
                mma8(acc[2], a0, a1, a2, a3,
                     __float_as_uint(w23.x), __float_as_uint(w23.y));
                mma8(acc[3], a0, a1, a2, a3,
                     __float_as_uint(w23.z), __float_as_uint(w23.w));
            }

            // ---- park K-partials ----
            {
                float* Pw = P + kw * (64 * P_STRIDE);
#pragma unroll
                for (int nt = 0; nt < 4; nt++) {
                    int col = nt * 8 + pcol;
                    Pw[prow * P_STRIDE + col]           = acc[nt][0];
                    Pw[prow * P_STRIDE + col + 1]       = acc[nt][1];
                    Pw[(prow + 8) * P_STRIDE + col]     = acc[nt][2];
                    Pw[(prow + 8) * P_STRIDE + col + 1] = acc[nt][3];
                }
            }
            __syncthreads();

            // ---- LSTM cell: 1 (b,j) per thread; K-reduce fused ----
            {
                float zi = xv0 + bh0;
                float zf = xv1 + bh1;
                float zg = xv2 + bh2;
                float zo = xv3 + bh3;
#pragma unroll
                for (int k = 0; k < 4; k++) {
                    const float* p = P + k * (64 * P_STRIDE) + cb * P_STRIDE;
                    zi += p[cjj];
                    zf += p[8 + cjj];
                    zg += p[16 + cjj];
                    zo += p[24 + cjj];
                }

                float ig = 1.f / (1.f + expf(-zi));
                float fg = 1.f / (1.f + expf(-zf));
                float gg = tanhf(zg);
                float og = 1.f / (1.f + expf(-zo));

                float cn = fg * c_old + ig * gg;
                float hn = og * tanhf(cn);

                if (phase == 0) {
                    hn = hn * mval + ho * (1.f - mval);
                    cn = cn * mval + c_old * (1.f - mval);
                } else {
                    dec_out[(size_t)(t * BB + cb) * NH + cj] = hn;
                }
                __stcg(h_out + fidx, to_tf32(hn));   // pre-round for next mma
                g_c[cb * NH + cj] = cn;
            }

            // ---- grid barrier: release-arrive + acquire-spin ----
            bar_target += NBLK;
            __syncthreads();                 // all block stores done
            if (tid == 0) {
                asm volatile("red.release.gpu.global.add.u32 [%0], %1;"
                             :: "l"(&g_bar), "r"(1u) : "memory");
                unsigned v;
                do {
                    asm volatile("ld.acquire.gpu.global.u32 %0, [%1];"
                                 : "=r"(v) : "l"(&g_bar) : "memory");
                } while (v < bar_target);
            }
            __syncthreads();
        }
    }
}

// ============================================================================
// kernel_launch: 4 graph nodes (init, 2x gemm, 1 persistent scan).
// ============================================================================
extern "C" void kernel_launch(void* const* d_in, const int* in_sizes, int n_in,
                              void* d_out, int out_size) {
    const float* input = (const float*)d_in[0];   // [T,B,NI]
    const float* mask  = (const float*)d_in[1];   // [T,B]
    const float* Wih_e = (const float*)d_in[2];   // [4H,NI]
    const float* Whh_e = (const float*)d_in[3];   // [4H,NH]
    const float* bih_e = (const float*)d_in[4];
    const float* bhh_e = (const float*)d_in[5];
    const float* Wih_d = (const float*)d_in[6];
    const float* Whh_d = (const float*)d_in[7];
    const float* bih_d = (const float*)d_in[8];
    const float* bhh_d = (const float*)d_in[9];
    float* out = (float*)d_out;                   // [T*B, NH]

    (void)in_sizes; (void)n_in; (void)out_size;

    static bool attr_set = false;
    if (!attr_set) {
        cudaFuncSetAttribute(lstm_scan,
                             cudaFuncAttributeMaxDynamicSharedMemorySize,
                             SCAN_SMEM_BYTES);
        attr_set = true;
    }

    // zero h/c/barrier state (mutated every run)
    init_state<<<256, 256>>>();

    // input projections for all timesteps (one big GEMM each)
    dim3 gg(NG / 128, (TT * BB) / 128);   // (32, 256)
    gemm_xw<<<gg, 256>>>(input, Wih_e, bih_e, 0);
    gemm_xw<<<gg, 256>>>(input, Wih_d, bih_d, 1);

    // full encoder + decoder scan in ONE persistent kernel
    lstm_scan<<<NBLK, 512, SCAN_SMEM_BYTES>>>(Whh_e, bhh_e, Whh_d, bhh_d,
                                              mask, out);
}